// round 14
// baseline (speedup 1.0000x reference)
#include <cuda_runtime.h>
#include <cuda.h>
#include <cuda_fp16.h>
#include <cstdint>

#define NB   2048
#define NT   512
#define NHID 1024
#define NVOC 31
#define EPS  1e-5f
#define NBLK 128
#define NTHR 512

#define KCH     64
#define NCHUNK  16
#define TILE16K 16384               // one 128x64 fp16 tile, 128B rows
#define STAGESZ 32768               // A tile + B tile
#define NSTAGE  3

// smem layout (dynamic)
#define OFF_MB    0                 // full[3]@0,8,16 ; empty[3]@24,32,40
#define OFF_XS    64                // 128 ints -> 576
#define OFF_S16   576               // sS half2[512] -> 2624
#define OFF_H16S  2624              // sH half2[512] -> 4672
#define OFF_GA    4672              // gamma -> 8768
#define OFF_BE    8768              // beta  -> 12864
#define OFF_CV    12864             // bho[32] -> 12992
#define OFF_RED   13056             // 32KB A-norm / C-partials -> 45824
#define OFF_WHO   45824             // 64KB Who16 swizzled (32 x 2048B) -> 111360
#define OFF_BUF   111360
#define SMEM_TOTAL (OFF_BUF + 1024 + NSTAGE * STAGESZ)   // 210688

// ---- persistent device state ----
__device__ __align__(128) uint16_t g_h16[3][NB * NHID];  // h fp16, 3 buffers (t%3)
__device__ __align__(128) uint16_t g_Wh[NHID * NHID];    // W_hh fp16 (TMA src)
__device__ __align__(128) uint16_t g_Who16[NVOC * NHID]; // W_ho fp16
__device__ __align__(16)  float    g_embW[NVOC * NHID];  // emb @ W^T + b_hh
__device__ __align__(16)  float    g_sum4[4][NHID];      // stats, 4-buffer rotation
__device__ __align__(16)  float    g_sumsq4[4][NHID];
__device__ __align__(128) unsigned g_cnt8[8 * 32];       // distributed iter counter
__device__ __align__(128) unsigned g_flagh[16 * 8 * 32]; // per (bm,bn) h-ready flag

// ============================ PTX helpers ============================
__device__ __forceinline__ uint32_t smem_to_u32(const void* p) {
    uint32_t a;
    asm("{ .reg .u64 t; cvta.to.shared.u64 t, %1; cvt.u32.u64 %0, t; }"
        : "=r"(a) : "l"(p));
    return a;
}
#define MBARRIER_INIT(mb, cnt) \
    asm volatile("mbarrier.init.shared.b64 [%0], %1;" \
                 :: "r"((uint32_t)(mb)), "r"((uint32_t)(cnt)) : "memory")
#define MBARRIER_ARRIVE(mb) \
    asm volatile("mbarrier.arrive.shared.b64 _, [%0];" \
                 :: "r"((uint32_t)(mb)) : "memory")
#define MBARRIER_EXPECT_TX(mb, bytes) \
    asm volatile("mbarrier.arrive.expect_tx.shared.b64 _, [%0], %1;" \
                 :: "r"((uint32_t)(mb)), "r"((uint32_t)(bytes)) : "memory")
#define MBARRIER_WAIT_PARITY(mb, ph) do {                                   \
    uint32_t _m = (uint32_t)(mb); uint32_t _p = (uint32_t)(ph);             \
    asm volatile("{\n\t.reg .pred P1;\n\t"                                  \
        "WAIT_LOOP_%=:\n\t"                                                 \
        "mbarrier.try_wait.parity.acquire.cta.shared::cta.b64 P1, [%0], %1, 0x989680;\n\t" \
        "@P1 bra.uni WAIT_DONE_%=;\n\t"                                     \
        "bra.uni WAIT_LOOP_%=;\n\t"                                         \
        "WAIT_DONE_%=:\n\t}" :: "r"(_m), "r"(_p) : "memory");               \
} while (0)
#define FENCE_PROXY_ASYNC() asm volatile("fence.proxy.async;" ::: "memory")

__device__ __forceinline__ void ldsm4(uint32_t* r, uint32_t addr) {
    asm volatile("ldmatrix.sync.aligned.m8n8.x4.shared.b16 {%0,%1,%2,%3}, [%4];"
                 : "=r"(r[0]), "=r"(r[1]), "=r"(r[2]), "=r"(r[3]) : "r"(addr));
}
__device__ __forceinline__ void mma16816(float* c, const uint32_t* a,
                                         uint32_t b0, uint32_t b1) {
    asm volatile(
        "mma.sync.aligned.m16n8k16.row.col.f32.f16.f16.f32 "
        "{%0,%1,%2,%3}, {%4,%5,%6,%7}, {%8,%9}, {%0,%1,%2,%3};"
        : "+f"(c[0]), "+f"(c[1]), "+f"(c[2]), "+f"(c[3])
        : "r"(a[0]), "r"(a[1]), "r"(a[2]), "r"(a[3]), "r"(b0), "r"(b1));
}

// TMA issue for global chunk G = t*16 + c : stage G%3, h-buffer (G>>4)%3.
// Polls the single producer block's ready flag before issuing.
__device__ __forceinline__ void issue_chunk(
    uint32_t sb, uint32_t bufabs,
    const CUtensorMap* mH, const CUtensorMap* mW,
    int bm, int m0, int n0, unsigned G)
{
    const unsigned tstep = G >> 4;
    const unsigned cc = G & 15u;
    if (tstep > 0) {
        volatile unsigned* f = &g_flagh[((unsigned)bm * 8u + (cc >> 1)) * 32u];
        while (*f < tstep) { }
        __threadfence();
    }
    const unsigned s = G % 3u;
    const unsigned u = G / 3u;
    MBARRIER_WAIT_PARITY(sb + OFF_MB + 24 + s * 8, (u & 1u) ^ 1u);
    MBARRIER_EXPECT_TX(sb + OFF_MB + s * 8, STAGESZ);
    const uint32_t dA = bufabs + s * STAGESZ;
    const int k0 = (int)cc * KCH;
    const int zb = (int)(tstep % 3u);
    asm volatile(
        "cp.async.bulk.tensor.3d.shared::cta.global.tile.mbarrier::complete_tx::bytes "
        "[%0], [%1, {%2, %3, %4}], [%5];"
        :: "r"(dA), "l"(mH), "r"(k0), "r"(m0), "r"(zb),
           "r"(sb + OFF_MB + s * 8) : "memory");
    asm volatile(
        "cp.async.bulk.tensor.2d.shared::cta.global.tile.mbarrier::complete_tx::bytes "
        "[%0], [%1, {%2, %3}], [%4];"
        :: "r"(dA + TILE16K), "l"(mW), "r"(k0), "r"(n0),
           "r"(sb + OFF_MB + s * 8) : "memory");
}

// ---------------------------------------------------------------------------
// init: zero h[0], stats, counters, flags; W_hh,W_ho -> fp16; embW
// ---------------------------------------------------------------------------
__global__ void k_init(const float* __restrict__ W, const float* __restrict__ emb,
                       const float* __restrict__ bhh, const float* __restrict__ Who) {
    int gid = blockIdx.x * blockDim.x + threadIdx.x;
    int stride = gridDim.x * blockDim.x;
    uint32_t* zA = (uint32_t*)g_h16[0];
    for (int i = gid; i < NB * NHID / 2; i += stride) zA[i] = 0u;
    for (int i = gid; i < NHID * NHID; i += stride)
        g_Wh[i] = __half_as_ushort(__float2half_rn(W[i]));
    if (gid < NVOC * NHID) {
        g_Who16[gid] = __half_as_ushort(__float2half_rn(Who[gid]));
        int v = gid >> 10, n = gid & (NHID - 1);
        const float4* er = (const float4*)(emb + (size_t)v * NHID);
        const float4* wr = (const float4*)(W + (size_t)n * NHID);
        float s0 = 0.f, s1 = 0.f, s2 = 0.f, s3 = 0.f;
        for (int k = 0; k < NHID / 4; k++) {
            float4 e = er[k], w = wr[k];
            s0 = fmaf(e.x, w.x, s0); s1 = fmaf(e.y, w.y, s1);
            s2 = fmaf(e.z, w.z, s2); s3 = fmaf(e.w, w.w, s3);
        }
        g_embW[gid] = (s0 + s1) + (s2 + s3) + bhh[n];
    }
    if (gid < NHID) {
        for (int r = 0; r < 4; r++) { g_sum4[r][gid] = 0.f; g_sumsq4[r][gid] = 0.f; }
    }
    if (gid < 8 * 32) g_cnt8[gid] = 0u;
    if (gid < 16 * 8 * 32) g_flagh[gid] = 0u;
}

// ---------------------------------------------------------------------------
// persistent kernel: 512 threads, 16 warps, warp tile 32x32
// ---------------------------------------------------------------------------
__global__ __launch_bounds__(NTHR, 1) void k_persist(
    const __grid_constant__ CUtensorMap mapH,
    const __grid_constant__ CUtensorMap mapW,
    const int* __restrict__ x,
    const float* __restrict__ bho,
    const float* __restrict__ gamma, const float* __restrict__ beta,
    float* __restrict__ out)
{
    extern __shared__ char smem[];
    const uint32_t sb = smem_to_u32(smem);
    const int tid = threadIdx.x;
    const int wid = tid >> 5;
    const int lane = tid & 31;
    const int b = blockIdx.x;
    const int bm = b >> 3;
    const int n0 = (b & 7) * 128;
    const int m0 = bm * 128;
    const int mw = wid >> 2;        // 0..3 : 32-row slice
    const int nw = wid & 3;         // 0..3 : 32-col slice

    int* xs = (int*)(smem + OFF_XS);
    float* sGa = (float*)(smem + OFF_GA);
    float* sBe = (float*)(smem + OFF_BE);
    float* cv = (float*)(smem + OFF_CV);
    const uint32_t bufabs = (sb + OFF_BUF + 1023) & ~1023u;
    const uint32_t Ared = sb + OFF_RED;
    const uint32_t Bwho = sb + OFF_WHO;

    // ldmatrix per-lane constants (phase 1)
    const uint32_t raA0 = (uint32_t)(mw * 32 + (lane & 15)) * 128;
    const uint32_t raA1 = raA0 + 16 * 128;
    const uint32_t rxA = (uint32_t)(lane & 7);
    const uint32_t rbB0 = (uint32_t)(nw * 32 + (lane & 15)) * 128;
    const uint32_t rbB1 = rbB0 + 16 * 128;
    const uint32_t rxB = rxA;
    const int hl = lane >> 4;

    if (tid == 0) {
        for (int s = 0; s < NSTAGE; s++) {
            MBARRIER_INIT(sb + OFF_MB + s * 8, 1);        // full: tx-based
            MBARRIER_INIT(sb + OFF_MB + 24 + s * 8, 16);  // empty: 16 warps
        }
        FENCE_PROXY_ASYNC();
    }
    sGa[tid] = gamma[tid]; sGa[tid + 512] = gamma[tid + 512];
    sBe[tid] = beta[tid];  sBe[tid + 512] = beta[tid + 512];
    if (tid < 32) cv[tid] = (tid < NVOC) ? bho[tid] : 0.f;
    if (tid < 128) xs[tid] = x[(m0 + tid) * NT + 0];

    // build swizzled Who16 in smem ONCE (row 31 zero)
    {
        const int v = tid >> 4, s0i = tid & 15;
#pragma unroll
        for (int i = 0; i < 8; i++) {
            int seg = s0i + i * 16;
            uint4 wq = make_uint4(0u, 0u, 0u, 0u);
            if (v < NVOC)
                wq = *(const uint4*)((const char*)g_Who16 + v * 2048 + seg * 16);
            *(uint4*)(smem + OFF_WHO + v * 2048 + ((seg ^ (v & 7)) << 4)) = wq;
        }
    }
    __syncthreads();

    if (tid == 0) {
        issue_chunk(sb, bufabs, &mapH, &mapW, bm, m0, n0, 0u);
        issue_chunk(sb, bufabs, &mapH, &mapW, bm, m0, n0, 1u);
    }

    for (int t = 0; t < NT; t++) {
        uint16_t* hn = g_h16[(t + 1) % 3];
        const int sp = t & 3;
        const unsigned Gbase = (unsigned)t * 16u;

        // ============ phase 1: h @ W^T via fp16 mma, TMA-fed ============
        float acc[2][4][4];
#pragma unroll
        for (int mt = 0; mt < 2; mt++)
#pragma unroll
            for (int j = 0; j < 4; j++)
#pragma unroll
                for (int q = 0; q < 4; q++) acc[mt][j][q] = 0.f;

        for (int c = 0; c < NCHUNK; c++) {
            if (tid == 0 && c + 2 < NCHUNK)
                issue_chunk(sb, bufabs, &mapH, &mapW, bm, m0, n0, Gbase + c + 2);
            const unsigned G = Gbase + c;
            const unsigned s = G % 3u;
            MBARRIER_WAIT_PARITY(sb + OFF_MB + s * 8, (G / 3u) & 1u);
            const uint32_t aB = bufabs + s * STAGESZ;
#pragma unroll
            for (int kt = 0; kt < 4; kt++) {
                const uint32_t segA = (uint32_t)(kt * 2 + hl);
                uint32_t a0[4], a1[4];
                {
                    uint32_t sa0 = aB + raA0 + ((segA ^ rxA) << 4);
                    uint32_t sa1 = aB + raA1 + ((segA ^ rxA) << 4);
                    ldsm4(a0, sa0); ldsm4(a1, sa1);
                }
                uint32_t bh[2][4];
                {
                    uint32_t sb0 = aB + TILE16K + rbB0 + ((segA ^ rxB) << 4);
                    uint32_t sb1 = aB + TILE16K + rbB1 + ((segA ^ rxB) << 4);
                    ldsm4(bh[0], sb0); ldsm4(bh[1], sb1);
                }
#pragma unroll
                for (int j = 0; j < 4; j++) {
                    const int g = j >> 1, o = j & 1;
                    mma16816(acc[0][j], a0, bh[g][o], bh[g][2 + o]);
                    mma16816(acc[1][j], a1, bh[g][o], bh[g][2 + o]);
                }
            }
            __syncwarp();
            if (lane == 0) MBARRIER_ARRIVE(sb + OFF_MB + 24 + s * 8);
        }

        // ============ epilogue: +embW[x], relu, fp16 store h, stats ========
        {
            const int cb = n0 + nw * 32 + (lane & 3) * 2;
            float csum[4][2], csq[4][2];
#pragma unroll
            for (int j = 0; j < 4; j++) {
                csum[j][0] = 0.f; csum[j][1] = 0.f;
                csq[j][0] = 0.f;  csq[j][1] = 0.f;
            }
#pragma unroll
            for (int mt = 0; mt < 2; mt++) {
#pragma unroll
                for (int rr = 0; rr < 2; rr++) {
                    const int lrow = mw * 32 + mt * 16 + rr * 8 + (lane >> 2);
                    const int row = m0 + lrow;
                    const float* ew = g_embW + (size_t)xs[lrow] * NHID;
                    uint16_t* dH = hn + (size_t)row * NHID;
#pragma unroll
                    for (int j = 0; j < 4; j++) {
                        const int col = cb + j * 8;
                        float2 e = *(const float2*)(ew + col);
                        float v0 = fmaxf(acc[mt][j][rr * 2 + 0] + e.x, 0.f);
                        float v1 = fmaxf(acc[mt][j][rr * 2 + 1] + e.y, 0.f);
                        __half2 hv = __floats2half2_rn(v0, v1);
                        *(uint32_t*)(dH + col) = *(uint32_t*)&hv;
                        csum[j][0] += v0; csum[j][1] += v1;
                        csq[j][0] = fmaf(v0, v0, csq[j][0]);
                        csq[j][1] = fmaf(v1, v1, csq[j][1]);
                    }
                }
            }
#pragma unroll
            for (int j = 0; j < 4; j++) {
                float s0 = csum[j][0], s1 = csum[j][1];
                float q0 = csq[j][0], q1 = csq[j][1];
                s0 += __shfl_down_sync(~0u, s0, 16);
                s1 += __shfl_down_sync(~0u, s1, 16);
                q0 += __shfl_down_sync(~0u, q0, 16);
                q1 += __shfl_down_sync(~0u, q1, 16);
                s0 += __shfl_down_sync(~0u, s0, 8);
                s1 += __shfl_down_sync(~0u, s1, 8);
                q0 += __shfl_down_sync(~0u, q0, 8);
                q1 += __shfl_down_sync(~0u, q1, 8);
                s0 += __shfl_down_sync(~0u, s0, 4);
                s1 += __shfl_down_sync(~0u, s1, 4);
                q0 += __shfl_down_sync(~0u, q0, 4);
                q1 += __shfl_down_sync(~0u, q1, 4);
                if (lane < 4) {
                    const int col = n0 + nw * 32 + j * 8 + lane * 2;
                    atomicAdd(&g_sum4[sp][col], s0);
                    atomicAdd(&g_sum4[sp][col + 1], s1);
                    atomicAdd(&g_sumsq4[sp][col], q0);
                    atomicAdd(&g_sumsq4[sp][col + 1], q1);
                }
            }
        }

        // ---- release h(t+1) flag; prefetch next step's chunks 0,1 ----
        __threadfence();
        __syncthreads();
        if (tid == 0) {
            FENCE_PROXY_ASYNC();
            atomicExch(&g_flagh[((unsigned)bm * 8u + (unsigned)(b & 7)) * 32u],
                       (unsigned)(t + 1));
            if (t < NT - 1) {
                issue_chunk(sb, bufabs, &mapH, &mapW, bm, m0, n0, Gbase + 16u);
                issue_chunk(sb, bufabs, &mapH, &mapW, bm, m0, n0, Gbase + 17u);
            }
        }

        // ============ deferred section: stats wait + phase3(t-1) ============
        if (t >= 1) {
            if (tid < 8) {
                volatile unsigned* c8 = &g_cnt8[tid * 32];
                while (*c8 < (unsigned)t * 16u) { }
                __threadfence();
            }
            __syncthreads();
            {
                const int spc = (t - 1) & 3;
                if (t >= 2) {
                    const int szp = (t - 2) & 3;
                    if (tid < 8) g_sum4[szp][b * 8 + tid] = 0.f;
                    else if (tid < 16) g_sumsq4[szp][b * 8 + tid - 8] = 0.f;
                }
                const int c0 = tid * 2;
                float mu0 = g_sum4[spc][c0] * (1.f / NB);
                float mu1 = g_sum4[spc][c0 + 1] * (1.f / NB);
                float vr0 = g_sumsq4[spc][c0] * (1.f / NB) - mu0 * mu0;
                float vr1 = g_sumsq4[spc][c0 + 1] * (1.f / NB) - mu1 * mu1;
                float sc0 = rsqrtf(vr0 + EPS) * sGa[c0];
                float sc1 = rsqrtf(vr1 + EPS) * sGa[c0 + 1];
                float sh0 = sBe[c0] - mu0 * sc0;
                float sh1 = sBe[c0 + 1] - mu1 * sc1;
                __half2 ps = __floats2half2_rn(sc0, sc1);
                __half2 ph = __floats2half2_rn(sh0, sh1);
                ((uint32_t*)(smem + OFF_S16))[tid] = *(uint32_t*)&ps;
                ((uint32_t*)(smem + OFF_H16S))[tid] = *(uint32_t*)&ph;
                if (t < NT - 1 && tid < 128) xs[tid] = x[(m0 + tid) * NT + t + 1];
            }
            __syncthreads();

            // phase3 for step t-1: h(t) = g_h16[t%3], out column t-1
            const uint16_t* hp3 = g_h16[t % 3];
            const int om0 = b * 16;
#pragma unroll
            for (int u = 0; u < 4; u++) {
                int idx = tid + u * 512;
                int row = idx >> 7, seg = idx & 127;
                uint4 d = *(const uint4*)(hp3 + (size_t)(om0 + row) * NHID + seg * 8);
                uint4 sv = ((const uint4*)(smem + OFF_S16))[seg];
                uint4 hv = ((const uint4*)(smem + OFF_H16S))[seg];
                uint4 r;
                {
                    __half2* dp = (__half2*)&d;
                    __half2* sp2 = (__half2*)&sv;
                    __half2* hp = (__half2*)&hv;
                    __half2* rp = (__half2*)&r;
#pragma unroll
                    for (int q = 0; q < 4; q++) rp[q] = __hfma2(dp[q], sp2[q], hp[q]);
                }
                *(uint4*)(smem + OFF_RED + row * 2048 + ((seg ^ (row & 7)) << 4)) = r;
            }
            __syncthreads();

            float pc[4][4];
#pragma unroll
            for (int j = 0; j < 4; j++)
#pragma unroll
                for (int q = 0; q < 4; q++) pc[j][q] = 0.f;
            {
                const int ks0 = wid * 64;
                const int arow = lane & 15;
                const int nrow0 = lane & 15;
                const int nrow1 = 16 + (lane & 15);
#pragma unroll
                for (int kt = 0; kt < 4; kt++) {
                    const int segk = ((ks0 + kt * 16) >> 3) + (lane >> 4);
                    uint32_t a[4];
                    ldsm4(a, Ared + arow * 2048 + ((segk ^ (arow & 7)) << 4));
                    uint32_t b0[4], b1[4];
                    ldsm4(b0, Bwho + nrow0 * 2048 + ((segk ^ (nrow0 & 7)) << 4));
                    ldsm4(b1, Bwho + nrow1 * 2048 + ((segk ^ (nrow1 & 7)) << 4));
#pragma unroll
                    for (int j = 0; j < 4; j++) {
                        const int o = j & 1;
                        if (j < 2) mma16816(pc[j], a, b0[o], b0[2 + o]);
                        else       mma16816(pc[j], a, b1[o], b1[2 + o]);
                    }
                }
            }
            __syncthreads();   // A reads done; reuse region for partials

#pragma unroll
            for (int j = 0; j < 4; j++) {
                const int r0 = lane >> 2;
                const int colb = j * 8 + (lane & 3) * 2;
                float2 lo = make_float2(pc[j][0], pc[j][1]);
                float2 hi = make_float2(pc[j][2], pc[j][3]);
                *(float2*)(smem + OFF_RED + wid * 2048 + r0 * 128 +
                           ((colb * 4 + r0 * 32) & 127)) = lo;
                const int r1 = r0 + 8;
                *(float2*)(smem + OFF_RED + wid * 2048 + r1 * 128 +
                           ((colb * 4 + r1 * 32) & 127)) = hi;
            }
            __syncthreads();

            {
                const int row = tid >> 5, col = tid & 31;
                float s = 0.f;
#pragma unroll
                for (int w = 0; w < 16; w++)
                    s += *(const float*)(smem + OFF_RED + w * 2048 + row * 128 +
                                         ((col * 4 + row * 32) & 127));
                if (col < NVOC) {
                    size_t orow = om0 + row;
                    out[orow * (size_t)(NT * NVOC) + (size_t)(t - 1) * NVOC + col] =
                        s + cv[col];
                }
            }
        } else {
            if (tid < 128) xs[tid] = x[(m0 + tid) * NT + 1];
            __syncthreads();
        }

        // ---- iteration-complete arrival ----
        __threadfence();
        __syncthreads();
        if (tid == 0) atomicAdd(&g_cnt8[(b & 7) * 32], 1u);
    }

    // ================= tail: phase3 for step NT-1 =================
    {
        if (tid < 8) {
            volatile unsigned* c8 = &g_cnt8[tid * 32];
            while (*c8 < (unsigned)NT * 16u) { }
            __threadfence();
        }
        __syncthreads();
        {
            const int spc = (NT - 1) & 3;
            const int c0 = tid * 2;
            float mu0 = g_sum4[spc][c0] * (1.f / NB);
            float mu1 = g_sum4[spc][c0 + 1] * (1.f / NB);
            float vr0 = g_sumsq4[spc][c0] * (1.f / NB) - mu0 * mu0;
            float vr1 = g_sumsq4[spc][c0 + 1] * (1.f / NB) - mu1 * mu1;
            float sc0 = rsqrtf(vr0 + EPS) * sGa[c0];
            float sc1 = rsqrtf(vr1 + EPS) * sGa[c0 + 1];
            float sh0 = sBe[c0] - mu0 * sc0;
            float sh1 = sBe[c0 + 1] - mu1 * sc1;
            __half2 ps = __floats2half2_rn(sc0, sc1);
            __half2 ph = __floats2half2_rn(sh0, sh1);
            ((uint32_t*)(smem + OFF_S16))[tid] = *(uint32_t*)&ps;
            ((uint32_t*)(smem + OFF_H16S))[tid] = *(uint32_t*)&ph;
        }
        __syncthreads();

        const uint16_t* hp3 = g_h16[NT % 3];
        const int om0 = b * 16;
#pragma unroll
        for (int u = 0; u < 4; u++) {
            int idx = tid + u * 512;
            int row = idx >> 7, seg = idx & 127;
            uint4 d = *(const uint4*)(hp3 + (size_t)(om0 + row) * NHID + seg * 8);
            uint4 sv = ((const uint4*)(smem + OFF_S16))[seg];
            uint4 hv = ((const uint4*)(smem + OFF_H16S))[seg];
            uint4 r;
            {
                __half2* dp = (__half2*)&d;
                __half2* sp2 = (__half2*)&sv;
                __half2* hp = (__half2*)&hv;
                __half2* rp = (__half2*)&r;
#pragma unroll
                for (int q = 0; q < 4; q++) rp[q] = __hfma2(dp[q], sp2[q], hp[q]);
            }
            *(uint4*)(smem + OFF_RED + row * 2048 + ((seg ^ (row & 7)) << 4)) = r;
        }
        __syncthreads();

        float pc[4][4];
#pragma unroll
        for (int j = 0; j < 4; j++)
#pragma unroll
            for (int q = 0; q < 4; q++) pc[j][q] = 0.f;
        {
            const int ks0 = wid * 64;
            const int arow = lane & 15;
            const int nrow0 = lane & 15;
            const int nrow1 = 16 + (lane & 15);
#pragma unroll
            for (int kt = 0; kt < 4; kt++) {
                const int segk = ((ks0 + kt * 16) >> 3) + (lane >> 4);
                uint32_t a[4];
                ldsm4(a, Ared + arow * 2048 + ((segk ^ (arow & 7)) << 4));
                uint32_t b0[4], b1[4];
                ldsm4(b0, Bwho + nrow0 * 2048 + ((segk ^ (nrow0 & 7)) << 4));
                ldsm4(b1, Bwho + nrow1 * 2048 + ((segk ^ (nrow1 & 7)) << 4));
#pragma unroll
                for (int j = 0; j < 4; j++) {
                    const int o = j & 1;
                    if (j < 2) mma16816(pc[j], a, b0[o], b0[2 + o]);
                    else       mma16816(pc[j], a, b1[o], b1[2 + o]);
                }
            }
        }
        __syncthreads();

#pragma unroll
        for (int j = 0; j < 4; j++) {
            const int r0 = lane >> 2;
            const int colb = j * 8 + (lane & 3) * 2;
            float2 lo = make_float2(pc[j][0], pc[j][1]);
            float2 hi = make_float2(pc[j][2], pc[j][3]);
            *(float2*)(smem + OFF_RED + wid * 2048 + r0 * 128 +
                       ((colb * 4 + r0 * 32) & 127)) = lo;
            const int r1 = r0 + 8;
            *(float2*)(smem + OFF_RED + wid * 2048 + r1 * 128 +
                       ((colb * 4 + r1 * 32) & 127)) = hi;
        }
        __syncthreads();

        {
            const int row = tid >> 5, col = tid & 31;
            float s = 0.f;
#pragma unroll
            for (int w = 0; w < 16; w++)
                s += *(const float*)(smem + OFF_RED + w * 2048 + row * 128 +
                                     ((col * 4 + row * 32) & 127));
            if (col < NVOC) {
                size_t orow = om0 + row;
                out[orow * (size_t)(NT * NVOC) + (size_t)(NT - 1) * NVOC + col] =
                    s + cv[col];
            }
        }
    }
}

// ---------------------------------------------------------------------------
typedef CUresult (CUDAAPI *PFN_tmap_enc)(
    CUtensorMap*, CUtensorMapDataType, cuuint32_t, void*,
    const cuuint64_t*, const cuuint64_t*, const cuuint32_t*, const cuuint32_t*,
    CUtensorMapInterleave, CUtensorMapSwizzle, CUtensorMapL2promotion,
    CUtensorMapFloatOOBfill);

extern "C" void kernel_launch(void* const* d_in, const int* in_sizes, int n_in,
                              void* d_out, int out_size)
{
    const int*   x     = (const int*)d_in[0];
    const float* emb   = (const float*)d_in[1];
    const float* Whh   = (const float*)d_in[2];
    const float* bhh   = (const float*)d_in[3];
    const float* Who   = (const float*)d_in[4];
    const float* bho   = (const float*)d_in[5];
    const float* gamma = (const float*)d_in[6];
    const float* beta  = (const float*)d_in[7];
    float* out = (float*)d_out;

    void* hsym = nullptr; cudaGetSymbolAddress(&hsym, g_h16);
    void* wsym = nullptr; cudaGetSymbolAddress(&wsym, g_Wh);
    PFN_tmap_enc enc = nullptr;
    cudaDriverEntryPointQueryResult qr;
    cudaGetDriverEntryPointByVersion("cuTensorMapEncodeTiled", (void**)&enc,
                                     12000, cudaEnableDefault, &qr);
    CUtensorMap mapH, mapW;
    {
        cuuint64_t dims[3] = {NHID, NB, 3};
        cuuint64_t strd[2] = {NHID * 2, (cuuint64_t)NB * NHID * 2};
        cuuint32_t box[3]  = {KCH, 128, 1};
        cuuint32_t es[3]   = {1, 1, 1};
        enc(&mapH, CU_TENSOR_MAP_DATA_TYPE_UINT16, 3, hsym, dims, strd, box, es,
            CU_TENSOR_MAP_INTERLEAVE_NONE, CU_TENSOR_MAP_SWIZZLE_128B,
            CU_TENSOR_MAP_L2_PROMOTION_L2_128B, CU_TENSOR_MAP_FLOAT_OOB_FILL_NONE);
    }
    {
        cuuint64_t dims[2] = {NHID, NHID};
        cuuint64_t strd[1] = {NHID * 2};
        cuuint32_t box[2]  = {KCH, 128};
        cuuint32_t es[2]   = {1, 1};
        enc(&mapW, CU_TENSOR_MAP_DATA_TYPE_UINT16, 2, wsym, dims, strd, box, es,
            CU_TENSOR_MAP_INTERLEAVE_NONE, CU_TENSOR_MAP_SWIZZLE_128B,
            CU_TENSOR_MAP_L2_PROMOTION_L2_128B, CU_TENSOR_MAP_FLOAT_OOB_FILL_NONE);
    }

    cudaFuncSetAttribute(k_persist, cudaFuncAttributeMaxDynamicSharedMemorySize,
                         SMEM_TOTAL);

    k_init<<<1024, 256>>>(Whh, emb, bhh, Who);
    k_persist<<<NBLK, NTHR, SMEM_TOTAL>>>(mapH, mapW, x, bho, gamma, beta, out);
}

// round 17
// speedup vs baseline: 1.3436x; 1.3436x over previous
#include <cuda_runtime.h>
#include <cuda.h>
#include <cuda_fp16.h>
#include <cstdint>

#define NB   2048
#define NT   512
#define NHID 1024
#define NVOC 31
#define EPS  1e-5f
#define NBLK 128
#define NTHR 512

#define KCH     64
#define NCHUNK  16
#define TILE16K 16384               // one 128x64 fp16 tile, 128B rows
#define STAGESZ 32768               // A tile + B tile
#define NSTAGE  3

// smem layout (dynamic)
#define OFF_MB    0                 // full[3]@0,8,16 ; empty[3]@24,32,40
#define OFF_XS    64                // 128 ints -> 576
#define OFF_S16   576               // sS half2[512] -> 2624
#define OFF_H16S  2624              // sH half2[512] -> 4672
#define OFF_GA    4672              // gamma -> 8768
#define OFF_BE    8768              // beta  -> 12864
#define OFF_CV    12864             // bho[32] -> 12992
#define OFF_RED   13056             // 32KB A-norm / C-partials -> 45824
#define OFF_WHO   45824             // 64KB Who16 swizzled (32 x 2048B) -> 111360
#define OFF_BUF   111360
#define SMEM_TOTAL (OFF_BUF + 1024 + NSTAGE * STAGESZ)   // 210688

// ---- persistent device state ----
__device__ __align__(128) uint16_t g_h16[2][NB * NHID];  // h fp16 (TMA src)
__device__ __align__(128) uint16_t g_Wh[NHID * NHID];    // W_hh fp16 (TMA src)
__device__ __align__(128) uint16_t g_Who16[NVOC * NHID]; // W_ho fp16
__device__ __align__(16)  float    g_embW[NVOC * NHID];  // emb @ W^T + b_hh
__device__ __align__(16)  float    g_sum3[3][NHID];
__device__ __align__(16)  float    g_sumsq3[3][NHID];
__device__ __align__(128) unsigned g_cnt8[8 * 32];       // distributed barrier

// ============================ PTX helpers ============================
__device__ __forceinline__ uint32_t smem_to_u32(const void* p) {
    uint32_t a;
    asm("{ .reg .u64 t; cvta.to.shared.u64 t, %1; cvt.u32.u64 %0, t; }"
        : "=r"(a) : "l"(p));
    return a;
}
#define MBARRIER_INIT(mb, cnt) \
    asm volatile("mbarrier.init.shared.b64 [%0], %1;" \
                 :: "r"((uint32_t)(mb)), "r"((uint32_t)(cnt)) : "memory")
#define MBARRIER_ARRIVE(mb) \
    asm volatile("mbarrier.arrive.shared.b64 _, [%0];" \
                 :: "r"((uint32_t)(mb)) : "memory")
#define MBARRIER_EXPECT_TX(mb, bytes) \
    asm volatile("mbarrier.arrive.expect_tx.shared.b64 _, [%0], %1;" \
                 :: "r"((uint32_t)(mb)), "r"((uint32_t)(bytes)) : "memory")
#define MBARRIER_WAIT_PARITY(mb, ph) do {                                   \
    uint32_t _m = (uint32_t)(mb); uint32_t _p = (uint32_t)(ph);             \
    asm volatile("{\n\t.reg .pred P1;\n\t"                                  \
        "WAIT_LOOP_%=:\n\t"                                                 \
        "mbarrier.try_wait.parity.acquire.cta.shared::cta.b64 P1, [%0], %1, 0x989680;\n\t" \
        "@P1 bra.uni WAIT_DONE_%=;\n\t"                                     \
        "bra.uni WAIT_LOOP_%=;\n\t"                                         \
        "WAIT_DONE_%=:\n\t}" :: "r"(_m), "r"(_p) : "memory");               \
} while (0)
#define FENCE_PROXY_ASYNC() asm volatile("fence.proxy.async;" ::: "memory")

__device__ __forceinline__ void ldsm4(uint32_t* r, uint32_t addr) {
    asm volatile("ldmatrix.sync.aligned.m8n8.x4.shared.b16 {%0,%1,%2,%3}, [%4];"
                 : "=r"(r[0]), "=r"(r[1]), "=r"(r[2]), "=r"(r[3]) : "r"(addr));
}
__device__ __forceinline__ void mma16816(float* c, const uint32_t* a,
                                         uint32_t b0, uint32_t b1) {
    asm volatile(
        "mma.sync.aligned.m16n8k16.row.col.f32.f16.f16.f32 "
        "{%0,%1,%2,%3}, {%4,%5,%6,%7}, {%8,%9}, {%0,%1,%2,%3};"
        : "+f"(c[0]), "+f"(c[1]), "+f"(c[2]), "+f"(c[3])
        : "r"(a[0]), "r"(a[1]), "r"(a[2]), "r"(a[3]), "r"(b0), "r"(b1));
}

// TMA issue for global chunk G = t*16 + c : stage G%3, h-buffer (G>>4)&1
__device__ __forceinline__ void issue_chunk(
    uint32_t sb, uint32_t bufabs,
    const CUtensorMap* mH, const CUtensorMap* mW,
    int m0, int n0, unsigned G)
{
    const unsigned s = G % 3u;
    const unsigned u = G / 3u;
    MBARRIER_WAIT_PARITY(sb + OFF_MB + 24 + s * 8, (u & 1u) ^ 1u);
    MBARRIER_EXPECT_TX(sb + OFF_MB + s * 8, STAGESZ);
    const uint32_t dA = bufabs + s * STAGESZ;
    const int k0 = (int)(G & 15u) * KCH;
    const int zb = (int)((G >> 4) & 1u);
    asm volatile(
        "cp.async.bulk.tensor.3d.shared::cta.global.tile.mbarrier::complete_tx::bytes "
        "[%0], [%1, {%2, %3, %4}], [%5];"
        :: "r"(dA), "l"(mH), "r"(k0), "r"(m0), "r"(zb),
           "r"(sb + OFF_MB + s * 8) : "memory");
    asm volatile(
        "cp.async.bulk.tensor.2d.shared::cta.global.tile.mbarrier::complete_tx::bytes "
        "[%0], [%1, {%2, %3}], [%4];"
        :: "r"(dA + TILE16K), "l"(mW), "r"(k0), "r"(n0),
           "r"(sb + OFF_MB + s * 8) : "memory");
}

// ---------------------------------------------------------------------------
// init: zero h[0] + counters; W_hh,W_ho -> fp16; embW = emb@W^T + b_hh
// ---------------------------------------------------------------------------
__global__ void k_init(const float* __restrict__ W, const float* __restrict__ emb,
                       const float* __restrict__ bhh, const float* __restrict__ Who) {
    int gid = blockIdx.x * blockDim.x + threadIdx.x;
    int stride = gridDim.x * blockDim.x;
    uint32_t* zA = (uint32_t*)g_h16[0];
    for (int i = gid; i < NB * NHID / 2; i += stride) zA[i] = 0u;
    for (int i = gid; i < NHID * NHID; i += stride)
        g_Wh[i] = __half_as_ushort(__float2half_rn(W[i]));
    if (gid < NVOC * NHID) {
        g_Who16[gid] = __half_as_ushort(__float2half_rn(Who[gid]));
        int v = gid >> 10, n = gid & (NHID - 1);
        const float4* er = (const float4*)(emb + (size_t)v * NHID);
        const float4* wr = (const float4*)(W + (size_t)n * NHID);
        float s0 = 0.f, s1 = 0.f, s2 = 0.f, s3 = 0.f;
        for (int k = 0; k < NHID / 4; k++) {
            float4 e = er[k], w = wr[k];
            s0 = fmaf(e.x, w.x, s0); s1 = fmaf(e.y, w.y, s1);
            s2 = fmaf(e.z, w.z, s2); s3 = fmaf(e.w, w.w, s3);
        }
        g_embW[gid] = (s0 + s1) + (s2 + s3) + bhh[n];
    }
    if (gid < NHID) {
        for (int r = 0; r < 3; r++) { g_sum3[r][gid] = 0.f; g_sumsq3[r][gid] = 0.f; }
    }
    if (gid < 8 * 32) g_cnt8[gid] = 0u;
}

// ---------------------------------------------------------------------------
// distributed grid barrier: 8 padded counters, 16 arrivals each
// ---------------------------------------------------------------------------
__device__ __forceinline__ void gridbar(unsigned& target, int b, int tid) {
    __syncthreads();
    target += 16;
    if (tid == 0) {
        __threadfence();
        FENCE_PROXY_ASYNC();
        atomicAdd(&g_cnt8[(b & 7) * 32], 1u);
    }
    if (tid < 8) {
        while (*(volatile unsigned*)&g_cnt8[tid * 32] < target) { }
        __threadfence();
    }
    __syncthreads();
}

// ---------------------------------------------------------------------------
// persistent kernel: 512 threads, 16 warps, warp tile 32x32
// ---------------------------------------------------------------------------
__global__ __launch_bounds__(NTHR, 1) void k_persist(
    const __grid_constant__ CUtensorMap mapH,
    const __grid_constant__ CUtensorMap mapW,
    const int* __restrict__ x,
    const float* __restrict__ bho,
    const float* __restrict__ gamma, const float* __restrict__ beta,
    float* __restrict__ out)
{
    extern __shared__ char smem[];
    const uint32_t sb = smem_to_u32(smem);
    const int tid = threadIdx.x;
    const int wid = tid >> 5;
    const int lane = tid & 31;
    const int b = blockIdx.x;
    const int n0 = (b & 7) * 128;
    const int m0 = (b >> 3) * 128;
    const int mw = wid >> 2;        // 0..3 : 32-row slice
    const int nw = wid & 3;         // 0..3 : 32-col slice

    int* xs = (int*)(smem + OFF_XS);
    float* sGa = (float*)(smem + OFF_GA);
    float* sBe = (float*)(smem + OFF_BE);
    float* cv = (float*)(smem + OFF_CV);
    const uint32_t bufabs = (sb + OFF_BUF + 1023) & ~1023u;
    const uint32_t Ared = sb + OFF_RED;
    const uint32_t Bwho = sb + OFF_WHO;

    // ldmatrix per-lane constants (phase 1)
    const uint32_t raA0 = (uint32_t)(mw * 32 + (lane & 15)) * 128;
    const uint32_t raA1 = raA0 + 16 * 128;
    const uint32_t rxA = (uint32_t)(lane & 7);
    const uint32_t rbB0 = (uint32_t)(nw * 32 + (lane & 15)) * 128;
    const uint32_t rbB1 = rbB0 + 16 * 128;
    const uint32_t rxB = rxA;
    const int hl = lane >> 4;

    // mbarrier init + preload gamma/beta/bho + xs(0)
    if (tid == 0) {
        for (int s = 0; s < NSTAGE; s++) {
            MBARRIER_INIT(sb + OFF_MB + s * 8, 1);        // full: tx-based
            MBARRIER_INIT(sb + OFF_MB + 24 + s * 8, 16);  // empty: 16 warps
        }
        FENCE_PROXY_ASYNC();
    }
    sGa[tid] = gamma[tid]; sGa[tid + 512] = gamma[tid + 512];
    sBe[tid] = beta[tid];  sBe[tid + 512] = beta[tid + 512];
    if (tid < 32) cv[tid] = (tid < NVOC) ? bho[tid] : 0.f;
    if (tid < 128) xs[tid] = x[(m0 + tid) * NT + 0];

    // build swizzled Who16 in smem ONCE (row 31 zero)
    {
        const int v = tid >> 4, s0i = tid & 15;
#pragma unroll
        for (int i = 0; i < 8; i++) {
            int seg = s0i + i * 16;
            uint4 wq = make_uint4(0u, 0u, 0u, 0u);
            if (v < NVOC)
                wq = *(const uint4*)((const char*)g_Who16 + v * 2048 + seg * 16);
            *(uint4*)(smem + OFF_WHO + v * 2048 + ((seg ^ (v & 7)) << 4)) = wq;
        }
    }
    __syncthreads();

    if (tid == 0) {
        issue_chunk(sb, bufabs, &mapH, &mapW, m0, n0, 0u);
        issue_chunk(sb, bufabs, &mapH, &mapW, m0, n0, 1u);
    }

    unsigned target = 0;

    for (int t = 0; t < NT; t++) {
        const int cur = t & 1;
        uint16_t* hn = g_h16[cur ^ 1];
        const int sp = t % 3;
        const unsigned Gbase = (unsigned)t * 16u;

        // ============ phase 1: h @ W^T via fp16 mma, TMA-fed ============
        float acc[2][4][4];
#pragma unroll
        for (int mt = 0; mt < 2; mt++)
#pragma unroll
            for (int j = 0; j < 4; j++)
#pragma unroll
                for (int q = 0; q < 4; q++) acc[mt][j][q] = 0.f;

        for (int c = 0; c < NCHUNK; c++) {
            const unsigned G = Gbase + c;
            const unsigned s = G % 3u;
            MBARRIER_WAIT_PARITY(sb + OFF_MB + s * 8, (G / 3u) & 1u);
            const uint32_t aB = bufabs + s * STAGESZ;
#pragma unroll
            for (int kt = 0; kt < 4; kt++) {
                const uint32_t segA = (uint32_t)(kt * 2 + hl);
                uint32_t a0[4], a1[4];
                {
                    uint32_t sa0 = aB + raA0 + ((segA ^ rxA) << 4);
                    uint32_t sa1 = aB + raA1 + ((segA ^ rxA) << 4);
                    ldsm4(a0, sa0); ldsm4(a1, sa1);
                }
                uint32_t bh[2][4];
                {
                    uint32_t sb0 = aB + TILE16K + rbB0 + ((segA ^ rxB) << 4);
                    uint32_t sb1 = aB + TILE16K + rbB1 + ((segA ^ rxB) << 4);
                    ldsm4(bh[0], sb0); ldsm4(bh[1], sb1);
                }
#pragma unroll
                for (int j = 0; j < 4; j++) {
                    const int g = j >> 1, o = j & 1;
                    mma16816(acc[0][j], a0, bh[g][o], bh[g][2 + o]);
                    mma16816(acc[1][j], a1, bh[g][o], bh[g][2 + o]);
                }
            }
            __syncwarp();
            if (lane == 0) MBARRIER_ARRIVE(sb + OFF_MB + 24 + s * 8);
            // issue chunk c+2 AFTER own mma: the empty-wait inside is then
            // nearly free (other warps have long arrived for chunk c-1)
            if (tid == 0 && c + 2 < NCHUNK)
                issue_chunk(sb, bufabs, &mapH, &mapW, m0, n0, G + 2u);
        }

        // ============ epilogue: +embW[x], relu, fp16 store h, stats ========
        {
            const int cb = n0 + nw * 32 + (lane & 3) * 2;
            float csum[4][2], csq[4][2];
#pragma unroll
            for (int j = 0; j < 4; j++) {
                csum[j][0] = 0.f; csum[j][1] = 0.f;
                csq[j][0] = 0.f;  csq[j][1] = 0.f;
            }
#pragma unroll
            for (int mt = 0; mt < 2; mt++) {
#pragma unroll
                for (int rr = 0; rr < 2; rr++) {
                    const int lrow = mw * 32 + mt * 16 + rr * 8 + (lane >> 2);
                    const int row = m0 + lrow;
                    const float* ew = g_embW + (size_t)xs[lrow] * NHID;
                    uint16_t* dH = hn + (size_t)row * NHID;
#pragma unroll
                    for (int j = 0; j < 4; j++) {
                        const int col = cb + j * 8;
                        float2 e = *(const float2*)(ew + col);
                        float v0 = fmaxf(acc[mt][j][rr * 2 + 0] + e.x, 0.f);
                        float v1 = fmaxf(acc[mt][j][rr * 2 + 1] + e.y, 0.f);
                        __half2 hv = __floats2half2_rn(v0, v1);
                        *(uint32_t*)(dH + col) = *(uint32_t*)&hv;
                        csum[j][0] += v0; csum[j][1] += v1;
                        csq[j][0] = fmaf(v0, v0, csq[j][0]);
                        csq[j][1] = fmaf(v1, v1, csq[j][1]);
                    }
                }
            }
#pragma unroll
            for (int j = 0; j < 4; j++) {
                float s0 = csum[j][0], s1 = csum[j][1];
                float q0 = csq[j][0], q1 = csq[j][1];
                s0 += __shfl_down_sync(~0u, s0, 16);
                s1 += __shfl_down_sync(~0u, s1, 16);
                q0 += __shfl_down_sync(~0u, q0, 16);
                q1 += __shfl_down_sync(~0u, q1, 16);
                s0 += __shfl_down_sync(~0u, s0, 8);
                s1 += __shfl_down_sync(~0u, s1, 8);
                q0 += __shfl_down_sync(~0u, q0, 8);
                q1 += __shfl_down_sync(~0u, q1, 8);
                s0 += __shfl_down_sync(~0u, s0, 4);
                s1 += __shfl_down_sync(~0u, s1, 4);
                q0 += __shfl_down_sync(~0u, q0, 4);
                q1 += __shfl_down_sync(~0u, q1, 4);
                if (lane < 4) {
                    const int col = n0 + nw * 32 + j * 8 + lane * 2;
                    atomicAdd(&g_sum3[sp][col], s0);
                    atomicAdd(&g_sum3[sp][col + 1], s1);
                    atomicAdd(&g_sumsq3[sp][col], q0);
                    atomicAdd(&g_sumsq3[sp][col + 1], q1);
                }
            }
        }

        gridbar(target, b, tid);

        // prefetch chunks 0,1 of step t+1 (h(t+1) now globally visible)
        if (t < NT - 1 && tid == 0) {
            issue_chunk(sb, bufabs, &mapH, &mapW, m0, n0, Gbase + 16u);
            issue_chunk(sb, bufabs, &mapH, &mapW, m0, n0, Gbase + 17u);
        }

        // ======== post-bar: zero stale stats; pack fp16 scale/shift ========
        {
            const int st = (t + 2) % 3;   // == (t-1) mod 3
            if (tid < 8) g_sum3[st][b * 8 + tid] = 0.f;
            else if (tid < 16) g_sumsq3[st][b * 8 + tid - 8] = 0.f;
            const int c0 = tid * 2;
            float mu0 = g_sum3[sp][c0] * (1.f / NB);
            float mu1 = g_sum3[sp][c0 + 1] * (1.f / NB);
            float vr0 = g_sumsq3[sp][c0] * (1.f / NB) - mu0 * mu0;
            float vr1 = g_sumsq3[sp][c0 + 1] * (1.f / NB) - mu1 * mu1;
            float sc0 = rsqrtf(vr0 + EPS) * sGa[c0];
            float sc1 = rsqrtf(vr1 + EPS) * sGa[c0 + 1];
            float sh0 = sBe[c0] - mu0 * sc0;
            float sh1 = sBe[c0 + 1] - mu1 * sc1;
            __half2 ps = __floats2half2_rn(sc0, sc1);
            __half2 ph = __floats2half2_rn(sh0, sh1);
            ((uint32_t*)(smem + OFF_S16))[tid] = *(uint32_t*)&ps;
            ((uint32_t*)(smem + OFF_H16S))[tid] = *(uint32_t*)&ph;
            if (t < NT - 1 && tid < 128) xs[tid] = x[(m0 + tid) * NT + t + 1];
        }
        __syncthreads();

        // ============ phase 3: out = norm(h) @ Who16^T + bho (MMA) =========
        {
            const int om0 = b * 16;
            // stage normalized A tile in fp16 (hfma2 folds BN)
#pragma unroll
            for (int u = 0; u < 4; u++) {
                int idx = tid + u * 512;
                int row = idx >> 7, seg = idx & 127;
                uint4 d = *(const uint4*)(hn + (size_t)(om0 + row) * NHID + seg * 8);
                uint4 sv = ((const uint4*)(smem + OFF_S16))[seg];
                uint4 hv = ((const uint4*)(smem + OFF_H16S))[seg];
                uint4 r;
                {
                    __half2* dp = (__half2*)&d;
                    __half2* sp2 = (__half2*)&sv;
                    __half2* hp = (__half2*)&hv;
                    __half2* rp = (__half2*)&r;
#pragma unroll
                    for (int q = 0; q < 4; q++) rp[q] = __hfma2(dp[q], sp2[q], hp[q]);
                }
                *(uint4*)(smem + OFF_RED + row * 2048 + ((seg ^ (row & 7)) << 4)) = r;
            }
            __syncthreads();

            // MMA: warp wid covers k-slice [wid*64, wid*64+64)
            float pc[4][4];
#pragma unroll
            for (int j = 0; j < 4; j++)
#pragma unroll
                for (int q = 0; q < 4; q++) pc[j][q] = 0.f;
            {
                const int ks0 = wid * 64;
                const int arow = lane & 15;
                const int nrow0 = lane & 15;
                const int nrow1 = 16 + (lane & 15);
#pragma unroll
                for (int kt = 0; kt < 4; kt++) {
                    const int segk = ((ks0 + kt * 16) >> 3) + (lane >> 4);
                    uint32_t a[4];
                    ldsm4(a, Ared + arow * 2048 + ((segk ^ (arow & 7)) << 4));
                    uint32_t b0[4], b1[4];
                    ldsm4(b0, Bwho + nrow0 * 2048 + ((segk ^ (nrow0 & 7)) << 4));
                    ldsm4(b1, Bwho + nrow1 * 2048 + ((segk ^ (nrow1 & 7)) << 4));
#pragma unroll
                    for (int j = 0; j < 4; j++) {
                        const int o = j & 1;
                        if (j < 2) mma16816(pc[j], a, b0[o], b0[2 + o]);
                        else       mma16816(pc[j], a, b1[o], b1[2 + o]);
                    }
                }
            }
            __syncthreads();   // A reads done; reuse region for partials

            // store partial C (16x32 per warp), bank-staggered
#pragma unroll
            for (int j = 0; j < 4; j++) {
                const int r0 = lane >> 2;
                const int colb = j * 8 + (lane & 3) * 2;
                float2 lo = make_float2(pc[j][0], pc[j][1]);
                float2 hi = make_float2(pc[j][2], pc[j][3]);
                *(float2*)(smem + OFF_RED + wid * 2048 + r0 * 128 +
                           ((colb * 4 + r0 * 32) & 127)) = lo;
                const int r1 = r0 + 8;
                *(float2*)(smem + OFF_RED + wid * 2048 + r1 * 128 +
                           ((colb * 4 + r1 * 32) & 127)) = hi;
            }
            __syncthreads();

            // reduce 16 partials, add bho, write out (streaming store)
            {
                const int row = tid >> 5, col = tid & 31;
                float s = 0.f;
#pragma unroll
                for (int w = 0; w < 16; w++)
                    s += *(const float*)(smem + OFF_RED + w * 2048 + row * 128 +
                                         ((col * 4 + row * 32) & 127));
                if (col < NVOC) {
                    size_t orow = om0 + row;
                    __stcs(&out[orow * (size_t)(NT * NVOC) +
                                (size_t)t * NVOC + col], s + cv[col]);
                }
            }
            // next write to OFF_RED is next step's phase 3 (after gridbar)
        }
    }
}

// ---------------------------------------------------------------------------
typedef CUresult (CUDAAPI *PFN_tmap_enc)(
    CUtensorMap*, CUtensorMapDataType, cuuint32_t, void*,
    const cuuint64_t*, const cuuint64_t*, const cuuint32_t*, const cuuint32_t*,
    CUtensorMapInterleave, CUtensorMapSwizzle, CUtensorMapL2promotion,
    CUtensorMapFloatOOBfill);

extern "C" void kernel_launch(void* const* d_in, const int* in_sizes, int n_in,
                              void* d_out, int out_size)
{
    const int*   x     = (const int*)d_in[0];
    const float* emb   = (const float*)d_in[1];
    const float* Whh   = (const float*)d_in[2];
    const float* bhh   = (const float*)d_in[3];
    const float* Who   = (const float*)d_in[4];
    const float* bho   = (const float*)d_in[5];
    const float* gamma = (const float*)d_in[6];
    const float* beta  = (const float*)d_in[7];
    float* out = (float*)d_out;

    void* hsym = nullptr; cudaGetSymbolAddress(&hsym, g_h16);
    void* wsym = nullptr; cudaGetSymbolAddress(&wsym, g_Wh);
    PFN_tmap_enc enc = nullptr;
    cudaDriverEntryPointQueryResult qr;
    cudaGetDriverEntryPointByVersion("cuTensorMapEncodeTiled", (void**)&enc,
                                     12000, cudaEnableDefault, &qr);
    CUtensorMap mapH, mapW;
    {
        cuuint64_t dims[3] = {NHID, NB, 2};
        cuuint64_t strd[2] = {NHID * 2, (cuuint64_t)NB * NHID * 2};
        cuuint32_t box[3]  = {KCH, 128, 1};
        cuuint32_t es[3]   = {1, 1, 1};
        enc(&mapH, CU_TENSOR_MAP_DATA_TYPE_UINT16, 3, hsym, dims, strd, box, es,
            CU_TENSOR_MAP_INTERLEAVE_NONE, CU_TENSOR_MAP_SWIZZLE_128B,
            CU_TENSOR_MAP_L2_PROMOTION_L2_128B, CU_TENSOR_MAP_FLOAT_OOB_FILL_NONE);
    }
    {
        cuuint64_t dims[2] = {NHID, NHID};
        cuuint64_t strd[1] = {NHID * 2};
        cuuint32_t box[2]  = {KCH, 128};
        cuuint32_t es[2]   = {1, 1};
        enc(&mapW, CU_TENSOR_MAP_DATA_TYPE_UINT16, 2, wsym, dims, strd, box, es,
            CU_TENSOR_MAP_INTERLEAVE_NONE, CU_TENSOR_MAP_SWIZZLE_128B,
            CU_TENSOR_MAP_L2_PROMOTION_L2_128B, CU_TENSOR_MAP_FLOAT_OOB_FILL_NONE);
    }

    cudaFuncSetAttribute(k_persist, cudaFuncAttributeMaxDynamicSharedMemorySize,
                         SMEM_TOTAL);

    k_init<<<1024, 256>>>(Whh, emb, bhh, Who);
    k_persist<<<NBLK, NTHR, SMEM_TOTAL>>>(mapH, mapW, x, bho, gamma, beta, out);
}